// round 1
// baseline (speedup 1.0000x reference)
#include <cuda_runtime.h>
#include <math_constants.h>

#define DD   128
#define HH   4
#define RNUM 2000
#define MAXM 768          // max members per region we buffer (mean 250, sd ~16 -> 32 sigma headroom)

// ---------------- scratch (static device globals; no allocs) ----------------
__device__ float g_a[HH * DD];     // folded q*Wk (pre-scaled by 1/sqrt(D))
__device__ float g_c[HH];          // folded q*bk (pre-scaled)
__device__ float g_qf[DD];         // full seed query S@Wq^T + bq
__device__ int   g_counts[RNUM];
__device__ int   g_starts[RNUM + 1];
__device__ int   g_cursor[RNUM];
__device__ int   g_deg[RNUM];
__device__ float g_dis[RNUM];
__device__ int   g_idx[1 << 20];   // sorted POI indices (N=500k fits)
__device__ float g_hg[RNUM * DD];  // O2 @ Wg^T

// ---------------- prep: q, a, c (1 block, 128 threads) ----------------
__global__ void k_prep(const float* __restrict__ S, const float* __restrict__ Wq,
                       const float* __restrict__ bq, const float* __restrict__ Wk,
                       const float* __restrict__ bk) {
    __shared__ float sS[DD];
    __shared__ float sqf[DD];
    int t = threadIdx.x;
    sS[t] = S[t];
    __syncthreads();
    // qf[t] = S . Wq[t,:] + bq[t]
    {
        const float4* wr = (const float4*)(Wq + t * DD);
        const float4* sv = (const float4*)sS;
        float s = 0.f;
#pragma unroll
        for (int j = 0; j < 32; j++) {
            float4 w = wr[j], v = sv[j];
            s += w.x * v.x + w.y * v.y + w.z * v.z + w.w * v.w;
        }
        s += bq[t];
        sqf[t] = s;
        g_qf[t] = s;
    }
    __syncthreads();
    const float scale = 0.08838834764831845f; // 1/sqrt(128)
    // a[h][j] = sum_dh qf[h*32+dh] * Wk[h*32+dh, j]
    for (int f = t; f < HH * DD; f += DD) {
        int h = f >> 7, j = f & 127;
        float acc = 0.f;
#pragma unroll
        for (int dh = 0; dh < 32; dh++)
            acc += sqf[h * 32 + dh] * Wk[(h * 32 + dh) * DD + j];
        g_a[f] = acc * scale;
    }
    if (t < HH) {
        float acc = 0.f;
#pragma unroll
        for (int dh = 0; dh < 32; dh++)
            acc += sqf[t * 32 + dh] * bk[t * 32 + dh];
        g_c[t] = acc * scale;
    }
}

// ---------------- sort prep ----------------
__global__ void k_zero() {
    int i = blockIdx.x * blockDim.x + threadIdx.x;
    if (i < RNUM) { g_counts[i] = 0; g_deg[i] = 1; } // deg starts at 1 (self loop)
}

__global__ void k_hist(const int* __restrict__ zone, int N) {
    int i = blockIdx.x * blockDim.x + threadIdx.x;
    if (i < N) atomicAdd(&g_counts[zone[i]], 1);
}

__global__ void k_deg(const int* __restrict__ dst, int E) {
    int i = blockIdx.x * blockDim.x + threadIdx.x;
    if (i < E) atomicAdd(&g_deg[dst[i]], 1);
}

// single-block scan over 2000 counts + dis = rsqrt(deg)
__global__ void k_scan() {
    __shared__ int sbuf[2][2048];
    int t = threadIdx.x; // 1024 threads
    for (int k = 0; k < 2; k++) {
        int i = t + k * 1024;
        sbuf[0][i] = (i < RNUM) ? g_counts[i] : 0;
    }
    __syncthreads();
    int src = 0;
    for (int off = 1; off < 2048; off <<= 1) {
        for (int k = 0; k < 2; k++) {
            int i = t + k * 1024;
            int v = sbuf[src][i];
            if (i >= off) v += sbuf[src][i - off];
            sbuf[1 - src][i] = v;
        }
        __syncthreads();
        src ^= 1;
    }
    for (int k = 0; k < 2; k++) {
        int i = t + k * 1024;
        if (i <= RNUM) g_starts[i] = (i == 0) ? 0 : sbuf[src][i - 1];
        if (i < RNUM) {
            g_cursor[i] = (i == 0) ? 0 : sbuf[src][i - 1];
            g_dis[i] = rsqrtf((float)g_deg[i]);
        }
    }
}

__global__ void k_scatter(const int* __restrict__ zone, int N) {
    int i = blockIdx.x * blockDim.x + threadIdx.x;
    if (i < N) {
        int pos = atomicAdd(&g_cursor[zone[i]], 1);
        g_idx[pos] = i;
    }
}

// ---------------- per-region: scores -> softmax -> P -> pooled -> O -> rFF -> Wg ----------------
__global__ __launch_bounds__(256) void k_region(
    const float* __restrict__ x, const float* __restrict__ Wv, const float* __restrict__ bv,
    const float* __restrict__ Wo, const float* __restrict__ bo, const float* __restrict__ Wg) {
    int r = blockIdx.x;
    int base = g_starts[r];
    int cnt = g_starts[r + 1] - base;
    if (cnt > MAXM) cnt = MAXM;

    __shared__ __align__(16) float sa[HH * DD];
    __shared__ float sc[HH];
    __shared__ __align__(16) float sw[MAXM * HH];   // scores, then exp weights
    __shared__ int   sidx[MAXM];
    __shared__ __align__(16) float sP[HH * DD];
    __shared__ __align__(16) float sO[DD];
    __shared__ __align__(16) float sO2[DD];
    __shared__ float s_m[HH], s_inv[HH];
    __shared__ float s_wred[8 * HH];
    __shared__ float s_part[256];

    int t = threadIdx.x;
    for (int i = t; i < HH * DD; i += 256) sa[i] = g_a[i];
    if (t < HH) sc[t] = g_c[t];
    for (int i = t; i < cnt; i += 256) sidx[i] = g_idx[base + i];
    __syncthreads();

    // ---- pass 1: scores + per-warp max (warp per member) ----
    int warp = t >> 5, lane = t & 31;
    float m0 = -CUDART_INF_F, m1 = -CUDART_INF_F, m2 = -CUDART_INF_F, m3 = -CUDART_INF_F;
    const float4* a0p = (const float4*)(sa + 0 * DD);
    const float4* a1p = (const float4*)(sa + 1 * DD);
    const float4* a2p = (const float4*)(sa + 2 * DD);
    const float4* a3p = (const float4*)(sa + 3 * DD);
    float4 a0 = a0p[lane], a1 = a1p[lane], a2 = a2p[lane], a3 = a3p[lane];
    for (int i = warp; i < cnt; i += 8) {
        int n = sidx[i];
        float4 xv = ((const float4*)x)[n * 32 + lane];
        float s0 = xv.x * a0.x + xv.y * a0.y + xv.z * a0.z + xv.w * a0.w;
        float s1 = xv.x * a1.x + xv.y * a1.y + xv.z * a1.z + xv.w * a1.w;
        float s2 = xv.x * a2.x + xv.y * a2.y + xv.z * a2.z + xv.w * a2.w;
        float s3 = xv.x * a3.x + xv.y * a3.y + xv.z * a3.z + xv.w * a3.w;
#pragma unroll
        for (int off = 16; off; off >>= 1) {
            s0 += __shfl_xor_sync(0xffffffffu, s0, off);
            s1 += __shfl_xor_sync(0xffffffffu, s1, off);
            s2 += __shfl_xor_sync(0xffffffffu, s2, off);
            s3 += __shfl_xor_sync(0xffffffffu, s3, off);
        }
        s0 += sc[0]; s1 += sc[1]; s2 += sc[2]; s3 += sc[3];
        if (lane == 0) {
            sw[i * 4 + 0] = s0; sw[i * 4 + 1] = s1;
            sw[i * 4 + 2] = s2; sw[i * 4 + 3] = s3;
        }
        m0 = fmaxf(m0, s0); m1 = fmaxf(m1, s1);
        m2 = fmaxf(m2, s2); m3 = fmaxf(m3, s3);
    }
    if (lane == 0) {
        s_wred[warp * 4 + 0] = m0; s_wred[warp * 4 + 1] = m1;
        s_wred[warp * 4 + 2] = m2; s_wred[warp * 4 + 3] = m3;
    }
    __syncthreads();
    if (t < HH) {
        float m = -CUDART_INF_F;
#pragma unroll
        for (int w = 0; w < 8; w++) m = fmaxf(m, s_wred[w * 4 + t]);
        s_m[t] = m;
    }
    __syncthreads();

    // ---- pass 1b: exp + segment sum per head ----
    {
        int h = t & 3;
        float mh = s_m[h];
        float loc = 0.f;
        for (int j = t; j < cnt * 4; j += 256) {
            float v = __expf(sw[j] - mh);
            sw[j] = v;
            loc += v;
        }
        s_part[t] = loc;
    }
    __syncthreads();
    if (t < HH) {
        float d = 0.f;
        for (int k = 0; k < 64; k++) d += s_part[t + 4 * k];
        s_inv[t] = (cnt > 0 && d > 0.f) ? (1.f / d) : 0.f;
    }
    __syncthreads();

    // ---- pass 2: P[h,d] = sum_i w[i,h] * x[n_i, d]  (unnormalized, scale at end) ----
    {
        int d = t & 127;
        int h0 = t >> 7; // 0 or 1; this thread also covers h0+2
        float acc0 = 0.f, acc1 = 0.f;
        int i = 0;
        for (; i + 4 <= cnt; i += 4) {
            int n0 = sidx[i], n1 = sidx[i + 1], n2 = sidx[i + 2], n3 = sidx[i + 3];
            float x0 = x[n0 * DD + d];
            float x1 = x[n1 * DD + d];
            float x2 = x[n2 * DD + d];
            float x3 = x[n3 * DD + d];
            acc0 += sw[(i + 0) * 4 + h0] * x0 + sw[(i + 1) * 4 + h0] * x1
                  + sw[(i + 2) * 4 + h0] * x2 + sw[(i + 3) * 4 + h0] * x3;
            acc1 += sw[(i + 0) * 4 + h0 + 2] * x0 + sw[(i + 1) * 4 + h0 + 2] * x1
                  + sw[(i + 2) * 4 + h0 + 2] * x2 + sw[(i + 3) * 4 + h0 + 2] * x3;
        }
        for (; i < cnt; i++) {
            int n = sidx[i];
            float xv = x[n * DD + d];
            acc0 += sw[i * 4 + h0] * xv;
            acc1 += sw[i * 4 + h0 + 2] * xv;
        }
        sP[h0 * DD + d] = acc0 * s_inv[h0];
        sP[(h0 + 2) * DD + d] = acc1 * s_inv[h0 + 2];
    }
    __syncthreads();

    float bvs = (cnt > 0) ? 1.f : 0.f; // empty region: pooled must be exactly 0

    // ---- pooled -> O (residual with seed query) ----
    if (t < DD) {
        int h = t >> 5;
        const float4* wr = (const float4*)(Wv + t * DD);
        const float4* pv = (const float4*)(sP + h * DD);
        float s = 0.f;
#pragma unroll
        for (int j = 0; j < 32; j++) {
            float4 w = wr[j], p = pv[j];
            s += w.x * p.x + w.y * p.y + w.z * p.z + w.w * p.w;
        }
        sO[t] = g_qf[t] + (s + bv[t]) * bvs;
    }
    __syncthreads();
    // ---- rFF residual ----
    if (t < DD) {
        const float4* wr = (const float4*)(Wo + t * DD);
        const float4* ov = (const float4*)sO;
        float s = 0.f;
#pragma unroll
        for (int j = 0; j < 32; j++) {
            float4 w = wr[j], o = ov[j];
            s += w.x * o.x + w.y * o.y + w.z * o.z + w.w * o.w;
        }
        s += bo[t];
        sO2[t] = sO[t] + fmaxf(s, 0.f);
    }
    __syncthreads();
    // ---- h = O2 @ Wg^T ----
    if (t < DD) {
        const float4* wr = (const float4*)(Wg + t * DD);
        const float4* ov = (const float4*)sO2;
        float s = 0.f;
#pragma unroll
        for (int j = 0; j < 32; j++) {
            float4 w = wr[j], o = ov[j];
            s += w.x * o.x + w.y * o.y + w.z * o.z + w.w * o.w;
        }
        g_hg[r * DD + t] = s;
    }
}

// ---------------- GCN ----------------
__global__ void k_gcn_init(float* __restrict__ out, const float* __restrict__ bg) {
    int i = blockIdx.x * blockDim.x + threadIdx.x;
    if (i < RNUM * DD) {
        int r = i >> 7, d = i & 127;
        float dis = g_dis[r];
        out[i] = bg[d] + dis * dis * g_hg[i];
    }
}

__global__ void k_gcn_edges(const int* __restrict__ src, const int* __restrict__ dst,
                            int E, float* __restrict__ out) {
    int tid = blockIdx.x * blockDim.x + threadIdx.x;
    int e = tid >> 5, lane = tid & 31;
    if (e < E) {
        int s = src[e], d = dst[e];
        float norm = g_dis[s] * g_dis[d];
        float4 hv = ((const float4*)g_hg)[s * 32 + lane];
        float* ob = out + d * DD + lane * 4;
        atomicAdd(ob + 0, norm * hv.x);
        atomicAdd(ob + 1, norm * hv.y);
        atomicAdd(ob + 2, norm * hv.z);
        atomicAdd(ob + 3, norm * hv.w);
    }
}

__global__ void k_prelu(float* __restrict__ out, const float* __restrict__ pw) {
    int i = blockIdx.x * blockDim.x + threadIdx.x;
    if (i < RNUM * DD) {
        float v = out[i];
        out[i] = (v > 0.f) ? v : pw[i & 127] * v;
    }
}

// ---------------- launch ----------------
extern "C" void kernel_launch(void* const* d_in, const int* in_sizes, int n_in,
                              void* d_out, int out_size) {
    const float* x    = (const float*)d_in[0];
    const int*   zone = (const int*)d_in[1];
    const int*   adj  = (const int*)d_in[2];
    const float* S    = (const float*)d_in[3];
    const float* Wq   = (const float*)d_in[4];
    const float* bq   = (const float*)d_in[5];
    const float* Wk   = (const float*)d_in[6];
    const float* bk   = (const float*)d_in[7];
    const float* Wv   = (const float*)d_in[8];
    const float* bv   = (const float*)d_in[9];
    const float* Wo   = (const float*)d_in[10];
    const float* bo   = (const float*)d_in[11];
    const float* Wg   = (const float*)d_in[12];
    const float* bg   = (const float*)d_in[13];
    const float* pw   = (const float*)d_in[14];
    float* out = (float*)d_out;

    int N = in_sizes[0] / DD;
    int E = in_sizes[2] / 2;
    const int* esrc = adj;
    const int* edst = adj + E;

    k_prep<<<1, 128>>>(S, Wq, bq, Wk, bk);
    k_zero<<<(RNUM + 255) / 256, 256>>>();
    k_hist<<<(N + 255) / 256, 256>>>(zone, N);
    k_deg<<<(E + 255) / 256, 256>>>(edst, E);
    k_scan<<<1, 1024>>>();
    k_scatter<<<(N + 255) / 256, 256>>>(zone, N);
    k_region<<<RNUM, 256>>>(x, Wv, bv, Wo, bo, Wg);
    k_gcn_init<<<(RNUM * DD + 255) / 256, 256>>>(out, bg);
    k_gcn_edges<<<(E * 32 + 255) / 256, 256>>>(esrc, edst, E, out);
    k_prelu<<<(RNUM * DD + 255) / 256, 256>>>(out, pw);
}

// round 2
// speedup vs baseline: 1.0215x; 1.0215x over previous
#include <cuda_runtime.h>
#include <math_constants.h>

#define DD   128
#define HH   4
#define RNUM 2000
#define MAXM 768
#define CH   32            // members per chunk
#define XST  132           // smem row stride in floats (33 float4s -> conflict-free)
#define NBUF 3

// ---------------- scratch (static device globals; zero-init at module load) ----------------
__device__ float g_a[HH * DD];     // folded q*Wk (pre-scaled by 1/sqrt(D))
__device__ float g_c[HH];          // folded q*bk (pre-scaled)
__device__ float g_qf[DD];         // seed query S@Wq^T + bq
__device__ int   g_counts[RNUM];   // invariant: zero at launch entry/exit
__device__ int   g_deg[RNUM];      // invariant: zero at launch entry/exit
__device__ int   g_starts[RNUM + 1];
__device__ int   g_cursor[RNUM];
__device__ float g_dis[RNUM];
__device__ int   g_idx[1 << 20];
__device__ float g_Px[RNUM * HH * DD];  // per-head weighted x-sum (4 MB)
__device__ float g_hg[RNUM * DD];       // O2 @ Wg^T

// ---------------- prep: q, a, c ----------------
__global__ void k_prep(const float* __restrict__ S, const float* __restrict__ Wq,
                       const float* __restrict__ bq, const float* __restrict__ Wk,
                       const float* __restrict__ bk) {
    __shared__ float sS[DD];
    __shared__ float sqf[DD];
    int t = threadIdx.x;
    sS[t] = S[t];
    __syncthreads();
    {
        const float4* wr = (const float4*)(Wq + t * DD);
        const float4* sv = (const float4*)sS;
        float s = 0.f;
#pragma unroll
        for (int j = 0; j < 32; j++) {
            float4 w = wr[j], v = sv[j];
            s += w.x * v.x + w.y * v.y + w.z * v.z + w.w * v.w;
        }
        s += bq[t];
        sqf[t] = s;
        g_qf[t] = s;
    }
    __syncthreads();
    const float scale = 0.08838834764831845f; // 1/sqrt(128)
    for (int f = t; f < HH * DD; f += DD) {
        int h = f >> 7, j = f & 127;
        float acc = 0.f;
#pragma unroll
        for (int dh = 0; dh < 32; dh++)
            acc += sqf[h * 32 + dh] * Wk[(h * 32 + dh) * DD + j];
        g_a[f] = acc * scale;
    }
    if (t < HH) {
        float acc = 0.f;
#pragma unroll
        for (int dh = 0; dh < 32; dh++)
            acc += sqf[t * 32 + dh] * bk[t * 32 + dh];
        g_c[t] = acc * scale;
    }
}

// ---------------- histogram (counts) + degree; counts/deg are zero on entry ----------------
__global__ void k_histdeg(const int* __restrict__ zone, int N,
                          const int* __restrict__ dst, int E) {
    int i = blockIdx.x * blockDim.x + threadIdx.x;
    if (i < N) atomicAdd(&g_counts[zone[i]], 1);
    if (i < E) atomicAdd(&g_deg[dst[i]], 1);
}

// scan counts -> starts/cursor; dis = rsqrt(deg+1); reset counts/deg for next replay
__global__ void k_scan() {
    __shared__ int sbuf[2][2048];
    int t = threadIdx.x; // 1024 threads
    for (int k = 0; k < 2; k++) {
        int i = t + k * 1024;
        sbuf[0][i] = (i < RNUM) ? g_counts[i] : 0;
    }
    __syncthreads();
    int src = 0;
    for (int off = 1; off < 2048; off <<= 1) {
        for (int k = 0; k < 2; k++) {
            int i = t + k * 1024;
            int v = sbuf[src][i];
            if (i >= off) v += sbuf[src][i - off];
            sbuf[1 - src][i] = v;
        }
        __syncthreads();
        src ^= 1;
    }
    for (int k = 0; k < 2; k++) {
        int i = t + k * 1024;
        if (i <= RNUM) g_starts[i] = (i == 0) ? 0 : sbuf[src][i - 1];
        if (i < RNUM) {
            g_cursor[i] = (i == 0) ? 0 : sbuf[src][i - 1];
            g_dis[i] = rsqrtf((float)(g_deg[i] + 1));
            g_counts[i] = 0;   // restore invariant for next launch
            g_deg[i] = 0;
        }
    }
}

__global__ void k_scatter(const int* __restrict__ zone, int N) {
    int i = blockIdx.x * blockDim.x + threadIdx.x;
    if (i < N) {
        int pos = atomicAdd(&g_cursor[zone[i]], 1);
        g_idx[pos] = i;
    }
}

// ---------------- region: one-pass online softmax + weighted x-sum ----------------
__device__ __forceinline__ void cp16(void* dst_smem, const void* src_gmem) {
    unsigned d = (unsigned)__cvta_generic_to_shared(dst_smem);
    asm volatile("cp.async.ca.shared.global [%0], [%1], 16;\n" :: "r"(d), "l"(src_gmem));
}
__device__ __forceinline__ void cp_commit() {
    asm volatile("cp.async.commit_group;\n" ::: "memory");
}
__device__ __forceinline__ void cp_wait0() {
    asm volatile("cp.async.wait_group 0;\n" ::: "memory");
}
__device__ __forceinline__ void cp_wait1() {
    asm volatile("cp.async.wait_group 1;\n" ::: "memory");
}

__global__ __launch_bounds__(256) void k_region(const float* __restrict__ x) {
    int r = blockIdx.x;
    int base = g_starts[r];
    int cnt = g_starts[r + 1] - base;
    if (cnt > MAXM) cnt = MAXM;
    int t = threadIdx.x;

    if (cnt == 0) {
        for (int o = t; o < HH * DD; o += 256) g_Px[r * (HH * DD) + o] = 0.f;
        return;
    }

    __shared__ __align__(16) float xs[NBUF][CH * XST];  // ~50.7 KB
    __shared__ __align__(16) float sa[HH * DD];
    __shared__ float sc[HH];
    __shared__ int   sidx[MAXM];
    __shared__ float s_s[CH * HH];
    __shared__ float s_w[CH * HH];
    __shared__ float s_m[HH], s_den[HH], s_scale[HH], s_inv[HH];

    for (int i = t; i < HH * DD; i += 256) sa[i] = g_a[i];
    if (t < HH) { sc[t] = g_c[t]; s_m[t] = -CUDART_INF_F; s_den[t] = 0.f; }
    for (int i = t; i < cnt; i += 256) sidx[i] = g_idx[base + i];
    __syncthreads();

    int warp = t >> 5, lane = t & 31;
    int nch = (cnt + CH - 1) / CH;

    // accumulators: group g = warp; thread covers d = lane*4..+3 for all 4 heads
    float4 acc[HH];
#pragma unroll
    for (int h = 0; h < HH; h++) acc[h] = make_float4(0.f, 0.f, 0.f, 0.f);

    // prologue: issue chunk 0
    {
        int cc = min(CH, cnt);
        for (int i = warp; i < cc; i += 8) {
            int n = sidx[i];
            cp16(&xs[0][i * XST + lane * 4], x + (size_t)n * DD + lane * 4);
        }
        cp_commit();
    }

    for (int c = 0; c < nch; c++) {
        int buf = c % NBUF;
        int cc = min(CH, cnt - c * CH);
        if (c + 1 < nch) {
            int nb = (c + 1) % NBUF;
            int cc1 = min(CH, cnt - (c + 1) * CH);
            for (int i = warp; i < cc1; i += 8) {
                int n = sidx[(c + 1) * CH + i];
                cp16(&xs[nb][i * XST + lane * 4], x + (size_t)n * DD + lane * 4);
            }
            cp_commit();
            cp_wait1();
        } else {
            cp_wait0();
        }
        __syncthreads();   // chunk c data ready

        // ---- scores: 128 threads, (i = t>>2, h = t&3), float4 dot from smem ----
        if (t < 128) {
            int i = t >> 2, h = t & 3;
            float sv = -CUDART_INF_F;
            if (i < cc) {
                const float4* xv = (const float4*)(xs[buf] + i * XST);
                const float4* av = (const float4*)(sa + h * DD);
                float s = 0.f;
#pragma unroll
                for (int j = 0; j < 32; j++) {
                    float4 xx = xv[j], aa = av[j];
                    s += xx.x * aa.x + xx.y * aa.y + xx.z * aa.z + xx.w * aa.w;
                }
                sv = s + sc[h];
            }
            s_s[i * HH + h] = sv;
        }
        __syncthreads();

        // ---- merge max, compute rescale factor ----
        if (t < HH) {
            float cm = -CUDART_INF_F;
#pragma unroll
            for (int i = 0; i < CH; i++) cm = fmaxf(cm, s_s[i * HH + t]);
            float nm = fmaxf(s_m[t], cm);
            s_scale[t] = __expf(s_m[t] - nm);   // 0 if prev m == -inf
            s_m[t] = nm;
        }
        __syncthreads();

        // ---- weights + rescale accumulators ----
        if (t < 128) {
            int i = t >> 2, h = t & 3;
            float w = 0.f;
            if (i < cc) w = __expf(s_s[i * HH + h] - s_m[h]);
            s_w[i * HH + h] = w;
        }
#pragma unroll
        for (int h = 0; h < HH; h++) {
            float sf = s_scale[h];
            acc[h].x *= sf; acc[h].y *= sf; acc[h].z *= sf; acc[h].w *= sf;
        }
        __syncthreads();

        // ---- denom update (4 threads) + weighted accumulation (all) ----
        if (t < HH) {
            float s = 0.f;
#pragma unroll
            for (int i = 0; i < CH; i++) s += s_w[i * HH + t];
            s_den[t] = s_den[t] * s_scale[t] + s;
        }
#pragma unroll 4
        for (int k = 0; k < 4; k++) {
            int i = warp * 4 + k;
            if (i < cc) {
                float4 xv = ((const float4*)(xs[buf] + i * XST))[lane];
                float w0 = s_w[i * HH + 0], w1 = s_w[i * HH + 1];
                float w2 = s_w[i * HH + 2], w3 = s_w[i * HH + 3];
                acc[0].x += w0 * xv.x; acc[0].y += w0 * xv.y; acc[0].z += w0 * xv.z; acc[0].w += w0 * xv.w;
                acc[1].x += w1 * xv.x; acc[1].y += w1 * xv.y; acc[1].z += w1 * xv.z; acc[1].w += w1 * xv.w;
                acc[2].x += w2 * xv.x; acc[2].y += w2 * xv.y; acc[2].z += w2 * xv.z; acc[2].w += w2 * xv.w;
                acc[3].x += w3 * xv.x; acc[3].y += w3 * xv.y; acc[3].z += w3 * xv.z; acc[3].w += w3 * xv.w;
            }
        }
        __syncthreads();   // protect xs[buf] reuse by later cp.async (NBUF=3 gives slack too)
    }

    if (t < HH) s_inv[t] = 1.f / s_den[t];

    // ---- reduce 8 partial groups; reuse xs[0] as scratch (8*4*132 = 4224 floats) ----
    __syncthreads();
    float* red = xs[0];
#pragma unroll
    for (int h = 0; h < HH; h++)
        ((float4*)(red + (warp * HH + h) * XST))[lane] = acc[h];
    __syncthreads();
    for (int o = t; o < HH * DD; o += 256) {
        int h = o >> 7, d = o & 127;
        float s = 0.f;
#pragma unroll
        for (int g = 0; g < 8; g++) s += red[(g * HH + h) * XST + d];
        g_Px[r * (HH * DD) + o] = s * s_inv[h];
    }
}

// ---------------- fused epilogue: pooled->O->rFF->Wg + GCN self-loop init ----------------
// 125 blocks x 16 rows, 512 threads (row-group rg = t>>7 covers 4 rows)
__global__ __launch_bounds__(512) void k_epi(
    const float* __restrict__ Wv, const float* __restrict__ bv,
    const float* __restrict__ Wo, const float* __restrict__ bo,
    const float* __restrict__ Wg, const float* __restrict__ bg,
    float* __restrict__ out) {
    int rb = blockIdx.x * 16;
    __shared__ __align__(16) float sPx[16 * 512];   // 32 KB
    __shared__ __align__(16) float sA[16 * XST];    // activations O
    __shared__ __align__(16) float sB[16 * XST];    // activations O2
    __shared__ float sqf[DD];
    __shared__ float sflag[16];
    int t = threadIdx.x;

    for (int i = t; i < 16 * 512; i += 512) sPx[i] = g_Px[rb * 512 + i];
    if (t < DD) sqf[t] = g_qf[t];
    if (t < 16) sflag[t] = (g_starts[rb + t + 1] > g_starts[rb + t]) ? 1.f : 0.f;
    __syncthreads();

    int d = t & 127, rg = t >> 7;      // rg in 0..3, rows rg*4..rg*4+3
    int h = d >> 5;

    // ---- stage 1: O = qf + (Px_h . Wv[d] + bv[d]) * flag ----
    {
        const float4* wv4 = (const float4*)(Wv + d * DD);
        float o0 = 0.f, o1 = 0.f, o2 = 0.f, o3 = 0.f;
#pragma unroll 8
        for (int j = 0; j < 32; j++) {
            float4 w = wv4[j];
            float4 p0 = ((const float4*)(sPx + (rg * 4 + 0) * 512 + h * DD))[j];
            float4 p1 = ((const float4*)(sPx + (rg * 4 + 1) * 512 + h * DD))[j];
            float4 p2 = ((const float4*)(sPx + (rg * 4 + 2) * 512 + h * DD))[j];
            float4 p3 = ((const float4*)(sPx + (rg * 4 + 3) * 512 + h * DD))[j];
            o0 += w.x * p0.x + w.y * p0.y + w.z * p0.z + w.w * p0.w;
            o1 += w.x * p1.x + w.y * p1.y + w.z * p1.z + w.w * p1.w;
            o2 += w.x * p2.x + w.y * p2.y + w.z * p2.z + w.w * p2.w;
            o3 += w.x * p3.x + w.y * p3.y + w.z * p3.z + w.w * p3.w;
        }
        float bvd = bv[d], qfd = sqf[d];
        sA[(rg * 4 + 0) * XST + d] = qfd + (o0 + bvd) * sflag[rg * 4 + 0];
        sA[(rg * 4 + 1) * XST + d] = qfd + (o1 + bvd) * sflag[rg * 4 + 1];
        sA[(rg * 4 + 2) * XST + d] = qfd + (o2 + bvd) * sflag[rg * 4 + 2];
        sA[(rg * 4 + 3) * XST + d] = qfd + (o3 + bvd) * sflag[rg * 4 + 3];
    }
    __syncthreads();

    // ---- stage 2: O2 = O + relu(O . Wo[d] + bo[d]) ----
    {
        const float4* wo4 = (const float4*)(Wo + d * DD);
        float o0 = 0.f, o1 = 0.f, o2 = 0.f, o3 = 0.f;
#pragma unroll 8
        for (int j = 0; j < 32; j++) {
            float4 w = wo4[j];
            float4 p0 = ((const float4*)(sA + (rg * 4 + 0) * XST))[j];
            float4 p1 = ((const float4*)(sA + (rg * 4 + 1) * XST))[j];
            float4 p2 = ((const float4*)(sA + (rg * 4 + 2) * XST))[j];
            float4 p3 = ((const float4*)(sA + (rg * 4 + 3) * XST))[j];
            o0 += w.x * p0.x + w.y * p0.y + w.z * p0.z + w.w * p0.w;
            o1 += w.x * p1.x + w.y * p1.y + w.z * p1.z + w.w * p1.w;
            o2 += w.x * p2.x + w.y * p2.y + w.z * p2.z + w.w * p2.w;
            o3 += w.x * p3.x + w.y * p3.y + w.z * p3.z + w.w * p3.w;
        }
        float bod = bo[d];
        sB[(rg * 4 + 0) * XST + d] = sA[(rg * 4 + 0) * XST + d] + fmaxf(o0 + bod, 0.f);
        sB[(rg * 4 + 1) * XST + d] = sA[(rg * 4 + 1) * XST + d] + fmaxf(o1 + bod, 0.f);
        sB[(rg * 4 + 2) * XST + d] = sA[(rg * 4 + 2) * XST + d] + fmaxf(o2 + bod, 0.f);
        sB[(rg * 4 + 3) * XST + d] = sA[(rg * 4 + 3) * XST + d] + fmaxf(o3 + bod, 0.f);
    }
    __syncthreads();

    // ---- stage 3: hg = O2 . Wg[d]; out init = bg + dis^2 * hg ----
    {
        const float4* wg4 = (const float4*)(Wg + d * DD);
        float o0 = 0.f, o1 = 0.f, o2 = 0.f, o3 = 0.f;
#pragma unroll 8
        for (int j = 0; j < 32; j++) {
            float4 w = wg4[j];
            float4 p0 = ((const float4*)(sB + (rg * 4 + 0) * XST))[j];
            float4 p1 = ((const float4*)(sB + (rg * 4 + 1) * XST))[j];
            float4 p2 = ((const float4*)(sB + (rg * 4 + 2) * XST))[j];
            float4 p3 = ((const float4*)(sB + (rg * 4 + 3) * XST))[j];
            o0 += w.x * p0.x + w.y * p0.y + w.z * p0.z + w.w * p0.w;
            o1 += w.x * p1.x + w.y * p1.y + w.z * p1.z + w.w * p1.w;
            o2 += w.x * p2.x + w.y * p2.y + w.z * p2.z + w.w * p2.w;
            o3 += w.x * p3.x + w.y * p3.y + w.z * p3.z + w.w * p3.w;
        }
        float bgd = bg[d];
#pragma unroll
        for (int k = 0; k < 4; k++) {
            int rr = rg * 4 + k;
            float hg = (k == 0) ? o0 : (k == 1) ? o1 : (k == 2) ? o2 : o3;
            int r = rb + rr;
            g_hg[r * DD + d] = hg;
            float dis = g_dis[r];
            out[r * DD + d] = bgd + dis * dis * hg;
        }
    }
}

// ---------------- GCN edges + PReLU ----------------
__global__ void k_gcn_edges(const int* __restrict__ src, const int* __restrict__ dst,
                            int E, float* __restrict__ out) {
    int tid = blockIdx.x * blockDim.x + threadIdx.x;
    int e = tid >> 5, lane = tid & 31;
    if (e < E) {
        int s = src[e], d = dst[e];
        float norm = g_dis[s] * g_dis[d];
        float4 hv = ((const float4*)g_hg)[s * 32 + lane];
        float* ob = out + d * DD + lane * 4;
        atomicAdd(ob + 0, norm * hv.x);
        atomicAdd(ob + 1, norm * hv.y);
        atomicAdd(ob + 2, norm * hv.z);
        atomicAdd(ob + 3, norm * hv.w);
    }
}

__global__ void k_prelu(float* __restrict__ out, const float* __restrict__ pw) {
    int i = blockIdx.x * blockDim.x + threadIdx.x;
    if (i < RNUM * DD) {
        float v = out[i];
        out[i] = (v > 0.f) ? v : pw[i & 127] * v;
    }
}

// ---------------- launch ----------------
extern "C" void kernel_launch(void* const* d_in, const int* in_sizes, int n_in,
                              void* d_out, int out_size) {
    const float* x    = (const float*)d_in[0];
    const int*   zone = (const int*)d_in[1];
    const int*   adj  = (const int*)d_in[2];
    const float* S    = (const float*)d_in[3];
    const float* Wq   = (const float*)d_in[4];
    const float* bq   = (const float*)d_in[5];
    const float* Wk   = (const float*)d_in[6];
    const float* bk   = (const float*)d_in[7];
    const float* Wv   = (const float*)d_in[8];
    const float* bv   = (const float*)d_in[9];
    const float* Wo   = (const float*)d_in[10];
    const float* bo   = (const float*)d_in[11];
    const float* Wg   = (const float*)d_in[12];
    const float* bg   = (const float*)d_in[13];
    const float* pw   = (const float*)d_in[14];
    float* out = (float*)d_out;

    int N = in_sizes[0] / DD;
    int E = in_sizes[2] / 2;
    const int* esrc = adj;
    const int* edst = adj + E;

    k_prep<<<1, 128>>>(S, Wq, bq, Wk, bk);
    k_histdeg<<<(N + 255) / 256, 256>>>(zone, N, edst, E);
    k_scan<<<1, 1024>>>();
    k_scatter<<<(N + 255) / 256, 256>>>(zone, N);
    k_region<<<RNUM, 256>>>(x);
    k_epi<<<RNUM / 16, 512>>>(Wv, bv, Wo, bo, Wg, bg, out);
    k_gcn_edges<<<(E * 32 + 255) / 256, 256>>>(esrc, edst, E, out);
    k_prelu<<<(RNUM * DD + 255) / 256, 256>>>(out, pw);
}

// round 3
// speedup vs baseline: 1.3674x; 1.3386x over previous
#include <cuda_runtime.h>
#include <math_constants.h>

#define DD   128
#define HH   4
#define RNUM 2000
#define MAXM 768
#define NCPY 32
#define XST  132

// ---------------- scratch ----------------
__device__ float  g_a[HH * DD];
__device__ float  g_c[HH];
__device__ float  g_qf[DD];
__device__ int    g_cnt32[NCPY * RNUM];   // invariant: zero at launch entry (scan resets)
__device__ int    g_cur32[NCPY * RNUM];
__device__ int    g_deg[RNUM];            // invariant: zero at entry (scan resets)
__device__ int    g_starts[RNUM + 1];
__device__ float  g_dis[RNUM];
__device__ int    g_idx[1 << 20];
__device__ float4 g_e4[1 << 19];          // exp-scores per POI (8 MB)
__device__ float  g_Px[RNUM * HH * DD];
__device__ float  g_hg[RNUM * DD];

// ---------------- launch 1: prep (block 0) + hist/deg (rest) ----------------
__global__ void k_prep_hist(const float* __restrict__ S, const float* __restrict__ Wq,
                            const float* __restrict__ bq, const float* __restrict__ Wk,
                            const float* __restrict__ bk,
                            const int* __restrict__ zone, int N,
                            const int* __restrict__ edst, int E) {
    int t = threadIdx.x;
    if (blockIdx.x == 0) {
        __shared__ float sS[DD], sqf[DD];
        if (t < DD) sS[t] = S[t];
        __syncthreads();
        if (t < DD) {
            const float4* wr = (const float4*)(Wq + t * DD);
            const float4* sv = (const float4*)sS;
            float s = 0.f;
#pragma unroll
            for (int j = 0; j < 32; j++) {
                float4 w = wr[j], v = sv[j];
                s += w.x * v.x + w.y * v.y + w.z * v.z + w.w * v.w;
            }
            s += bq[t];
            sqf[t] = s;
            g_qf[t] = s;
        }
        __syncthreads();
        const float scale = 0.08838834764831845f; // 1/sqrt(128)
        for (int f = t; f < HH * DD; f += 256) {
            int h = f >> 7, j = f & 127;
            float acc = 0.f;
#pragma unroll
            for (int dh = 0; dh < 32; dh++)
                acc += sqf[h * 32 + dh] * Wk[(h * 32 + dh) * DD + j];
            g_a[f] = acc * scale;
        }
        if (t < HH) {
            float acc = 0.f;
#pragma unroll
            for (int dh = 0; dh < 32; dh++)
                acc += sqf[t * 32 + dh] * bk[t * 32 + dh];
            g_c[t] = acc * scale;
        }
        return;
    }
    int i = (blockIdx.x - 1) * 256 + t;
    if (i < N) {
        int c = (i >> 8) & (NCPY - 1);
        atomicAdd(&g_cnt32[c * RNUM + zone[i]], 1);
    }
    if (i < E) atomicAdd(&g_deg[edst[i]], 1);
}

// ---------------- launch 2: scan + per-copy cursor bases + dis + reset ----------------
__global__ void k_scan() {
    __shared__ int sbuf[2][2048];
    int t = threadIdx.x; // 1024
    for (int k = 0; k < 2; k++) {
        int r = t + k * 1024;
        int tot = 0;
        if (r < RNUM)
            for (int c = 0; c < NCPY; c++) tot += g_cnt32[c * RNUM + r];
        sbuf[0][r] = tot;
    }
    __syncthreads();
    int src = 0;
    for (int off = 1; off < 2048; off <<= 1) {
        for (int k = 0; k < 2; k++) {
            int i = t + k * 1024;
            int v = sbuf[src][i];
            if (i >= off) v += sbuf[src][i - off];
            sbuf[1 - src][i] = v;
        }
        __syncthreads();
        src ^= 1;
    }
    for (int k = 0; k < 2; k++) {
        int r = t + k * 1024;
        if (r <= RNUM) g_starts[r] = (r == 0) ? 0 : sbuf[src][r - 1];
        if (r < RNUM) {
            int run = (r == 0) ? 0 : sbuf[src][r - 1];
            for (int c = 0; c < NCPY; c++) {
                int v = g_cnt32[c * RNUM + r];
                g_cur32[c * RNUM + r] = run;
                run += v;
                g_cnt32[c * RNUM + r] = 0;   // restore invariant
            }
            g_dis[r] = rsqrtf((float)(g_deg[r] + 1));
            g_deg[r] = 0;
        }
    }
}

// ---------------- launch 3: scatter (blocks < SB) + coalesced scores (rest) ----------------
__global__ __launch_bounds__(256) void k_scatter_scores(
    const float* __restrict__ x, const int* __restrict__ zone, int N, int SB, int GB) {
    int bid = blockIdx.x, t = threadIdx.x;
    if (bid < SB) {
        int i = bid * 256 + t;
        if (i < N) {
            int z = zone[i];
            int c = (i >> 8) & (NCPY - 1);
            int pos = atomicAdd(&g_cur32[c * RNUM + z], 1);
            g_idx[pos] = i;
        }
        return;
    }
    __shared__ __align__(16) float4 sa4[HH * 32];
    __shared__ float sc[HH];
    for (int i = t; i < HH * DD; i += 256) ((float*)sa4)[i] = g_a[i];
    if (t < HH) sc[t] = g_c[t];
    __syncthreads();

    int warp = t >> 5, lane = t & 31, sub = lane >> 3, sl = lane & 7;
    for (long long chunk = bid - SB; chunk * 32 < (long long)N; chunk += GB) {
        int row = (int)(chunk * 32) + warp * 4 + sub;
        bool ok = row < N;
        int rowc = ok ? row : 0;
        const float4* xr = (const float4*)(x + (size_t)rowc * DD);
        float p0 = 0.f, p1 = 0.f, p2 = 0.f, p3 = 0.f;
#pragma unroll
        for (int k = 0; k < 4; k++) {
            float4 xv = xr[sl * 4 + k];
            float4 a0 = sa4[0 * 32 + sl * 4 + k];
            float4 a1 = sa4[1 * 32 + sl * 4 + k];
            float4 a2 = sa4[2 * 32 + sl * 4 + k];
            float4 a3 = sa4[3 * 32 + sl * 4 + k];
            p0 += xv.x * a0.x + xv.y * a0.y + xv.z * a0.z + xv.w * a0.w;
            p1 += xv.x * a1.x + xv.y * a1.y + xv.z * a1.z + xv.w * a1.w;
            p2 += xv.x * a2.x + xv.y * a2.y + xv.z * a2.z + xv.w * a2.w;
            p3 += xv.x * a3.x + xv.y * a3.y + xv.z * a3.z + xv.w * a3.w;
        }
#pragma unroll
        for (int off = 1; off < 8; off <<= 1) {
            p0 += __shfl_xor_sync(0xffffffffu, p0, off);
            p1 += __shfl_xor_sync(0xffffffffu, p1, off);
            p2 += __shfl_xor_sync(0xffffffffu, p2, off);
            p3 += __shfl_xor_sync(0xffffffffu, p3, off);
        }
        if (ok && sl == 0) {
            float4 e;
            e.x = __expf(p0 + sc[0]);
            e.y = __expf(p1 + sc[1]);
            e.z = __expf(p2 + sc[2]);
            e.w = __expf(p3 + sc[3]);
            g_e4[row] = e;
        }
    }
}

// ---------------- launch 4: region weighted-sum (barrier-free mainloop) ----------------
__global__ __launch_bounds__(256) void k_region(const float* __restrict__ x) {
    int r = blockIdx.x;
    int base = g_starts[r];
    int cnt = g_starts[r + 1] - base;
    if (cnt > MAXM) cnt = MAXM;
    int t = threadIdx.x;

    if (cnt == 0) {
        for (int o = t; o < HH * DD; o += 256) g_Px[r * (HH * DD) + o] = 0.f;
        return;
    }

    __shared__ int   sidx[MAXM];
    __shared__ __align__(16) float red[8 * HH * DD];   // 16 KB
    __shared__ float sden[8 * HH];
    __shared__ float sinv[HH];

    for (int i = t; i < cnt; i += 256) sidx[i] = g_idx[base + i];
    __syncthreads();

    int warp = t >> 5, lane = t & 31;
    float4 a0 = make_float4(0.f, 0.f, 0.f, 0.f), a1 = a0, a2 = a0, a3 = a0;
    float d0 = 0.f, d1 = 0.f, d2 = 0.f, d3 = 0.f;

    int i = warp;
    for (; i + 8 < cnt; i += 16) {
        int n0 = sidx[i], n1 = sidx[i + 8];
        float4 e0 = __ldg(&g_e4[n0]);
        float4 e1 = __ldg(&g_e4[n1]);
        float4 x0 = __ldg((const float4*)(x + (size_t)n0 * DD) + lane);
        float4 x1 = __ldg((const float4*)(x + (size_t)n1 * DD) + lane);
        a0.x += e0.x * x0.x; a0.y += e0.x * x0.y; a0.z += e0.x * x0.z; a0.w += e0.x * x0.w;
        a1.x += e0.y * x0.x; a1.y += e0.y * x0.y; a1.z += e0.y * x0.z; a1.w += e0.y * x0.w;
        a2.x += e0.z * x0.x; a2.y += e0.z * x0.y; a2.z += e0.z * x0.z; a2.w += e0.z * x0.w;
        a3.x += e0.w * x0.x; a3.y += e0.w * x0.y; a3.z += e0.w * x0.z; a3.w += e0.w * x0.w;
        d0 += e0.x; d1 += e0.y; d2 += e0.z; d3 += e0.w;
        a0.x += e1.x * x1.x; a0.y += e1.x * x1.y; a0.z += e1.x * x1.z; a0.w += e1.x * x1.w;
        a1.x += e1.y * x1.x; a1.y += e1.y * x1.y; a1.z += e1.y * x1.z; a1.w += e1.y * x1.w;
        a2.x += e1.z * x1.x; a2.y += e1.z * x1.y; a2.z += e1.z * x1.z; a2.w += e1.z * x1.w;
        a3.x += e1.w * x1.x; a3.y += e1.w * x1.y; a3.z += e1.w * x1.z; a3.w += e1.w * x1.w;
        d0 += e1.x; d1 += e1.y; d2 += e1.z; d3 += e1.w;
    }
    for (; i < cnt; i += 8) {
        int n = sidx[i];
        float4 e = __ldg(&g_e4[n]);
        float4 xv = __ldg((const float4*)(x + (size_t)n * DD) + lane);
        a0.x += e.x * xv.x; a0.y += e.x * xv.y; a0.z += e.x * xv.z; a0.w += e.x * xv.w;
        a1.x += e.y * xv.x; a1.y += e.y * xv.y; a1.z += e.y * xv.z; a1.w += e.y * xv.w;
        a2.x += e.z * xv.x; a2.y += e.z * xv.y; a2.z += e.z * xv.z; a2.w += e.z * xv.w;
        a3.x += e.w * xv.x; a3.y += e.w * xv.y; a3.z += e.w * xv.z; a3.w += e.w * xv.w;
        d0 += e.x; d1 += e.y; d2 += e.z; d3 += e.w;
    }

    ((float4*)(red + (warp * HH + 0) * DD))[lane] = a0;
    ((float4*)(red + (warp * HH + 1) * DD))[lane] = a1;
    ((float4*)(red + (warp * HH + 2) * DD))[lane] = a2;
    ((float4*)(red + (warp * HH + 3) * DD))[lane] = a3;
    if (lane == 0) {
        sden[warp * HH + 0] = d0; sden[warp * HH + 1] = d1;
        sden[warp * HH + 2] = d2; sden[warp * HH + 3] = d3;
    }
    __syncthreads();
    if (t < HH) {
        float s = 0.f;
#pragma unroll
        for (int g = 0; g < 8; g++) s += sden[g * HH + t];
        sinv[t] = 1.f / s;
    }
    __syncthreads();
    for (int o = t; o < HH * DD; o += 256) {
        int h = o >> 7, d = o & 127;
        float s = 0.f;
#pragma unroll
        for (int g = 0; g < 8; g++) s += red[(g * HH + h) * DD + d];
        g_Px[r * (HH * DD) + o] = s * sinv[h];
    }
}

// ---------------- launch 5: fused dense epilogue ----------------
__global__ __launch_bounds__(512) void k_epi(
    const float* __restrict__ Wv, const float* __restrict__ bv,
    const float* __restrict__ Wo, const float* __restrict__ bo,
    const float* __restrict__ Wg, const float* __restrict__ bg,
    float* __restrict__ out) {
    int rb = blockIdx.x * 16;
    __shared__ __align__(16) float sPx[16 * 512];
    __shared__ __align__(16) float sA[16 * XST];
    __shared__ __align__(16) float sB[16 * XST];
    __shared__ float sqf[DD];
    __shared__ float sflag[16];
    int t = threadIdx.x;

    for (int i = t; i < 16 * 512; i += 512) sPx[i] = g_Px[rb * 512 + i];
    if (t < DD) sqf[t] = g_qf[t];
    if (t < 16) sflag[t] = (g_starts[rb + t + 1] > g_starts[rb + t]) ? 1.f : 0.f;
    __syncthreads();

    int d = t & 127, rg = t >> 7;
    int h = d >> 5;
    {
        const float4* wv4 = (const float4*)(Wv + d * DD);
        float o0 = 0.f, o1 = 0.f, o2 = 0.f, o3 = 0.f;
#pragma unroll 8
        for (int j = 0; j < 32; j++) {
            float4 w = wv4[j];
            float4 p0 = ((const float4*)(sPx + (rg * 4 + 0) * 512 + h * DD))[j];
            float4 p1 = ((const float4*)(sPx + (rg * 4 + 1) * 512 + h * DD))[j];
            float4 p2 = ((const float4*)(sPx + (rg * 4 + 2) * 512 + h * DD))[j];
            float4 p3 = ((const float4*)(sPx + (rg * 4 + 3) * 512 + h * DD))[j];
            o0 += w.x * p0.x + w.y * p0.y + w.z * p0.z + w.w * p0.w;
            o1 += w.x * p1.x + w.y * p1.y + w.z * p1.z + w.w * p1.w;
            o2 += w.x * p2.x + w.y * p2.y + w.z * p2.z + w.w * p2.w;
            o3 += w.x * p3.x + w.y * p3.y + w.z * p3.z + w.w * p3.w;
        }
        float bvd = bv[d], qfd = sqf[d];
        sA[(rg * 4 + 0) * XST + d] = qfd + (o0 + bvd) * sflag[rg * 4 + 0];
        sA[(rg * 4 + 1) * XST + d] = qfd + (o1 + bvd) * sflag[rg * 4 + 1];
        sA[(rg * 4 + 2) * XST + d] = qfd + (o2 + bvd) * sflag[rg * 4 + 2];
        sA[(rg * 4 + 3) * XST + d] = qfd + (o3 + bvd) * sflag[rg * 4 + 3];
    }
    __syncthreads();
    {
        const float4* wo4 = (const float4*)(Wo + d * DD);
        float o0 = 0.f, o1 = 0.f, o2 = 0.f, o3 = 0.f;
#pragma unroll 8
        for (int j = 0; j < 32; j++) {
            float4 w = wo4[j];
            float4 p0 = ((const float4*)(sA + (rg * 4 + 0) * XST))[j];
            float4 p1 = ((const float4*)(sA + (rg * 4 + 1) * XST))[j];
            float4 p2 = ((const float4*)(sA + (rg * 4 + 2) * XST))[j];
            float4 p3 = ((const float4*)(sA + (rg * 4 + 3) * XST))[j];
            o0 += w.x * p0.x + w.y * p0.y + w.z * p0.z + w.w * p0.w;
            o1 += w.x * p1.x + w.y * p1.y + w.z * p1.z + w.w * p1.w;
            o2 += w.x * p2.x + w.y * p2.y + w.z * p2.z + w.w * p2.w;
            o3 += w.x * p3.x + w.y * p3.y + w.z * p3.z + w.w * p3.w;
        }
        float bod = bo[d];
        sB[(rg * 4 + 0) * XST + d] = sA[(rg * 4 + 0) * XST + d] + fmaxf(o0 + bod, 0.f);
        sB[(rg * 4 + 1) * XST + d] = sA[(rg * 4 + 1) * XST + d] + fmaxf(o1 + bod, 0.f);
        sB[(rg * 4 + 2) * XST + d] = sA[(rg * 4 + 2) * XST + d] + fmaxf(o2 + bod, 0.f);
        sB[(rg * 4 + 3) * XST + d] = sA[(rg * 4 + 3) * XST + d] + fmaxf(o3 + bod, 0.f);
    }
    __syncthreads();
    {
        const float4* wg4 = (const float4*)(Wg + d * DD);
        float o0 = 0.f, o1 = 0.f, o2 = 0.f, o3 = 0.f;
#pragma unroll 8
        for (int j = 0; j < 32; j++) {
            float4 w = wg4[j];
            float4 p0 = ((const float4*)(sB + (rg * 4 + 0) * XST))[j];
            float4 p1 = ((const float4*)(sB + (rg * 4 + 1) * XST))[j];
            float4 p2 = ((const float4*)(sB + (rg * 4 + 2) * XST))[j];
            float4 p3 = ((const float4*)(sB + (rg * 4 + 3) * XST))[j];
            o0 += w.x * p0.x + w.y * p0.y + w.z * p0.z + w.w * p0.w;
            o1 += w.x * p1.x + w.y * p1.y + w.z * p1.z + w.w * p1.w;
            o2 += w.x * p2.x + w.y * p2.y + w.z * p2.z + w.w * p2.w;
            o3 += w.x * p3.x + w.y * p3.y + w.z * p3.z + w.w * p3.w;
        }
        float bgd = bg[d];
#pragma unroll
        for (int k = 0; k < 4; k++) {
            int rr = rg * 4 + k;
            float hg = (k == 0) ? o0 : (k == 1) ? o1 : (k == 2) ? o2 : o3;
            int r = rb + rr;
            g_hg[r * DD + d] = hg;
            float dis = g_dis[r];
            out[r * DD + d] = bgd + dis * dis * hg;
        }
    }
}

// ---------------- launch 6/7: GCN edges + PReLU ----------------
__global__ void k_gcn_edges(const int* __restrict__ src, const int* __restrict__ dst,
                            int E, float* __restrict__ out) {
    int tid = blockIdx.x * blockDim.x + threadIdx.x;
    int e = tid >> 5, lane = tid & 31;
    if (e < E) {
        int s = src[e], d = dst[e];
        float norm = g_dis[s] * g_dis[d];
        float4 hv = ((const float4*)g_hg)[s * 32 + lane];
        float* ob = out + d * DD + lane * 4;
        atomicAdd(ob + 0, norm * hv.x);
        atomicAdd(ob + 1, norm * hv.y);
        atomicAdd(ob + 2, norm * hv.z);
        atomicAdd(ob + 3, norm * hv.w);
    }
}

__global__ void k_prelu(float* __restrict__ out, const float* __restrict__ pw) {
    int i = blockIdx.x * blockDim.x + threadIdx.x;
    if (i < RNUM * DD) {
        float v = out[i];
        out[i] = (v > 0.f) ? v : pw[i & 127] * v;
    }
}

// ---------------- launch ----------------
extern "C" void kernel_launch(void* const* d_in, const int* in_sizes, int n_in,
                              void* d_out, int out_size) {
    const float* x    = (const float*)d_in[0];
    const int*   zone = (const int*)d_in[1];
    const int*   adj  = (const int*)d_in[2];
    const float* S    = (const float*)d_in[3];
    const float* Wq   = (const float*)d_in[4];
    const float* bq   = (const float*)d_in[5];
    const float* Wk   = (const float*)d_in[6];
    const float* bk   = (const float*)d_in[7];
    const float* Wv   = (const float*)d_in[8];
    const float* bv   = (const float*)d_in[9];
    const float* Wo   = (const float*)d_in[10];
    const float* bo   = (const float*)d_in[11];
    const float* Wg   = (const float*)d_in[12];
    const float* bg   = (const float*)d_in[13];
    const float* pw   = (const float*)d_in[14];
    float* out = (float*)d_out;

    int N = in_sizes[0] / DD;
    int E = in_sizes[2] / 2;
    const int* esrc = adj;
    const int* edst = adj + E;

    int NE = (N > E) ? N : E;
    int SB = (N + 255) / 256;
    int GB = 2368;

    k_prep_hist<<<1 + (NE + 255) / 256, 256>>>(S, Wq, bq, Wk, bk, zone, N, edst, E);
    k_scan<<<1, 1024>>>();
    k_scatter_scores<<<SB + GB, 256>>>(x, zone, N, SB, GB);
    k_region<<<RNUM, 256>>>(x);
    k_epi<<<RNUM / 16, 512>>>(Wv, bv, Wo, bo, Wg, bg, out);
    k_gcn_edges<<<(E * 32 + 255) / 256, 256>>>(esrc, edst, E, out);
    k_prelu<<<(RNUM * DD + 255) / 256, 256>>>(out, pw);
}